// round 10
// baseline (speedup 1.0000x reference)
#include <cuda_runtime.h>
#include <math.h>

#define NN 50000
#define EE 600000
#define DD 128
#define CC 8
#define SCALEF 0.08838834764831845f   // 128^-0.5
#define NBLK 196                       // scan blocks: ceil(50000/256)
#define FCAP 64                        // smem edge cap per node

// ---------------- static device scratch ----------------
__device__ __align__(16) int   g_deg[NN];
__device__ __align__(16) int   g_rowptr[NN + 1];
__device__ __align__(16) int   g_cursor[NN];
__device__ __align__(16) int   g_eids[EE];
__device__ __align__(16) int   g_bsum[NBLK];
__device__ __align__(16) int   g_boff[NBLK];
__device__ __align__(16) float g_WkT[DD * DD];
__device__ __align__(16) float g_Wqk[DD * DD];
__device__ __align__(16) float g_Wvo[DD * DD];
__device__ __align__(16) float g_bqk[DD];
__device__ __align__(16) float g_bvo[DD];
__device__ __align__(16) float g_wqbk[DD];
__device__            float g_bqbk;
__device__ __align__(16) float g_qp[(size_t)NN * DD];
__device__ __align__(16) float g_qb[NN];
__device__ __align__(16) float g_exo[EE];    // overflow ex/cf (deg>FCAP only)
__device__ __align__(16) int   g_aso[EE];    // overflow assign
__device__ __align__(16) int   g_cflag[CC];
__device__ __align__(16) float g_U[(size_t)NN * DD];
__device__ __align__(16) float g_S[NN];

// ---------------- packed f32x2 helpers ----------------
__device__ __forceinline__ unsigned long long pack2(float x) {
    unsigned long long r;
    unsigned u = __float_as_uint(x);
    asm("mov.b64 %0, {%1, %1};" : "=l"(r) : "r"(u));
    return r;
}
__device__ __forceinline__ void ffma2(unsigned long long& d, unsigned long long a,
                                      unsigned long long b) {
    asm("fma.rn.f32x2 %0, %1, %2, %0;" : "+l"(d) : "l"(a), "l"(b));
}
__device__ __forceinline__ void unpack2(unsigned long long v, float& lo, float& hi) {
    unsigned a, b;
    asm("mov.b64 {%0, %1}, %2;" : "=r"(a), "=r"(b) : "l"(v));
    lo = __uint_as_float(a); hi = __uint_as_float(b);
}
__device__ __forceinline__ float dot4(float4 a, float4 b) {
    return a.x * b.x + a.y * b.y + a.z * b.z + a.w * b.w;
}

// ---------------- prep + init fused ----------------
__global__ void k_prep(const float* __restrict__ Wq, const float* __restrict__ bq,
                       const float* __restrict__ Wk, const float* __restrict__ bk,
                       const float* __restrict__ bv, const float* __restrict__ Wo) {
    int b = blockIdx.x;
    if (b < DD) {
        int r = b, c = threadIdx.x;
        g_WkT[c * DD + r] = Wk[r * DD + c];
    } else if (b == DD) {
        int j = threadIdx.x;
        float s1 = 0.f, s2 = 0.f, s3 = 0.f;
        for (int l = 0; l < DD; l++) {
            s1 += bq[l] * Wk[j * DD + l];      // bqk  = bq @ Wk^T
            s2 += bv[l] * Wo[l * DD + j];      // bvo  = bv @ Wo
            s3 += Wq[j * DD + l] * bk[l];      // wqbk = Wq @ bk
        }
        g_bqk[j] = s1; g_bvo[j] = s2; g_wqbk[j] = s3;
        if (j < CC) g_cflag[j] = 0;
        if (j == 0) {
            float t = 0.f;
            for (int l = 0; l < DD; l++) t += bq[l] * bk[l];
            g_bqbk = t;
        }
    } else {
        int i = (b - DD - 1) * blockDim.x + threadIdx.x;
        if (i < NN) g_deg[i] = 0;
    }
}

// ---------------- CSR build ----------------
__global__ void k_hist(const int* __restrict__ src) {
    int i = blockIdx.x * blockDim.x + threadIdx.x;
    if (i < EE) atomicAdd(&g_deg[src[i]], 1);
}

__global__ void k_scanA() {
    __shared__ int red[256];
    int i = blockIdx.x * 256 + threadIdx.x;
    int v = (i < NN) ? g_deg[i] : 0;
    red[threadIdx.x] = v;
    __syncthreads();
    for (int off = 128; off; off >>= 1) {
        if (threadIdx.x < off) red[threadIdx.x] += red[threadIdx.x + off];
        __syncthreads();
    }
    if (threadIdx.x == 0) g_bsum[blockIdx.x] = red[0];
}

__global__ void k_scanB() {
    __shared__ int s[256];
    int tid = threadIdx.x;
    int v = (tid < NBLK) ? g_bsum[tid] : 0;
    s[tid] = v;
    __syncthreads();
    for (int off = 1; off < 256; off <<= 1) {
        int t = (tid >= off) ? s[tid - off] : 0;
        __syncthreads();
        s[tid] += t;
        __syncthreads();
    }
    if (tid < NBLK) g_boff[tid] = s[tid] - v;
    if (tid == 255) g_rowptr[NN] = s[255];
}

__global__ void k_scanC() {
    __shared__ int s[256];
    int tid = threadIdx.x;
    int i = blockIdx.x * 256 + tid;
    int v = (i < NN) ? g_deg[i] : 0;
    s[tid] = v;
    __syncthreads();
    for (int off = 1; off < 256; off <<= 1) {
        int t = (tid >= off) ? s[tid - off] : 0;
        __syncthreads();
        s[tid] += t;
        __syncthreads();
    }
    if (i < NN) {
        int e = g_boff[blockIdx.x] + s[tid] - v;
        g_rowptr[i] = e;
        g_cursor[i] = e;
    }
}

__global__ void k_scatter(const int* __restrict__ src) {
    int i = blockIdx.x * blockDim.x + threadIdx.x;
    if (i < EE) {
        int p = atomicAdd(&g_cursor[src[i]], 1);
        g_eids[p] = i;
    }
}

// ---------------- [M,128] @ [128,128] GEMM (R6 shape, measured ~49us) -------
__global__ void __launch_bounds__(256, 2)
k_gemm128(const float* __restrict__ A, const float* __restrict__ W,
          const float* __restrict__ bias, const float* __restrict__ rowscale,
          const float* __restrict__ vecterm, float* __restrict__ out,
          int M, int doRelu, int doQb, int useInvnn) {
    extern __shared__ float smem[];
    float4* Ws4 = (float4*)smem;                 // 128*128 floats (64KB)
    float4* As4 = (float4*)(smem + DD * DD);     // 64*128 floats (32KB)
    const ulonglong2* WsU = (const ulonglong2*)smem;

    for (int i = threadIdx.x; i < DD * DD / 4; i += blockDim.x)
        Ws4[i] = ((const float4*)W)[i];
    __syncthreads();

    int r = threadIdx.x >> 5;    // 0..7 row group (uniform per warp)
    int jc = threadIdx.x & 31;   // 0..31 col group (4 cols)

    float gs = 1.f;
    if (useInvnn) {
        int nn = 0;
#pragma unroll
        for (int c = 0; c < CC; c++) nn += g_cflag[c];
        if (nn < 1) nn = 1;
        gs = 1.f / (float)nn;
    }

    for (int tile = blockIdx.x; tile * 64 < M; tile += gridDim.x) {
        int row0 = tile * 64;
        for (int i = threadIdx.x; i < 64 * 32; i += blockDim.x) {
            int rr = i >> 5, cc = i & 31;
            float4 v = make_float4(0.f, 0.f, 0.f, 0.f);
            if (row0 + rr < M) v = ((const float4*)A)[(size_t)(row0 + rr) * 32 + cc];
            As4[i] = v;
        }
        __syncthreads();

        unsigned long long acc2[8][2];
#pragma unroll
        for (int a = 0; a < 8; a++) { acc2[a][0] = 0ull; acc2[a][1] = 0ull; }

#pragma unroll 2
        for (int k4 = 0; k4 < 32; k4++) {
            float4 a4[8];
#pragma unroll
            for (int rr = 0; rr < 8; rr++) a4[rr] = As4[(r * 8 + rr) * 32 + k4];  // broadcast
#pragma unroll
            for (int kk = 0; kk < 4; kk++) {
                int k = k4 * 4 + kk;
                ulonglong2 w = WsU[k * 32 + jc];
#pragma unroll
                for (int rr = 0; rr < 8; rr++) {
                    float av = (kk == 0) ? a4[rr].x : (kk == 1) ? a4[rr].y
                             : (kk == 2) ? a4[rr].z : a4[rr].w;
                    unsigned long long av2 = pack2(av);
                    ffma2(acc2[rr][0], av2, w.x);
                    ffma2(acc2[rr][1], av2, w.y);
                }
            }
        }

        if (doQb) {
            float4 wq = ((const float4*)g_wqbk)[jc];
#pragma unroll
            for (int rr = 0; rr < 8; rr++) {
                int row = row0 + r * 8 + rr;
                float4 a0 = As4[(r * 8 + rr) * 32 + jc];
                float part = dot4(a0, wq);
#pragma unroll
                for (int off = 16; off; off >>= 1)
                    part += __shfl_xor_sync(0xffffffffu, part, off);
                if (jc == 0 && row < M) g_qb[row] = part + g_bqbk;
            }
        }

        float bv4[4] = {0,0,0,0}, vv4[4] = {0,0,0,0};
        if (bias) {
            float4 b0 = ((const float4*)bias)[jc];
            bv4[0]=b0.x; bv4[1]=b0.y; bv4[2]=b0.z; bv4[3]=b0.w;
        }
        if (vecterm) {
            float4 v0 = ((const float4*)vecterm)[jc];
            vv4[0]=v0.x; vv4[1]=v0.y; vv4[2]=v0.z; vv4[3]=v0.w;
        }

#pragma unroll
        for (int rr = 0; rr < 8; rr++) {
            int row = row0 + r * 8 + rr;
            if (row < M) {
                float sc = rowscale ? rowscale[row] : 0.f;
                float o[4];
                unpack2(acc2[rr][0], o[0], o[1]);
                unpack2(acc2[rr][1], o[2], o[3]);
#pragma unroll
                for (int c = 0; c < 4; c++) {
                    o[c] = gs * (o[c] + sc * vv4[c]) + bv4[c];
                    if (doRelu) o[c] = fmaxf(o[c], 0.f);
                }
                ((float4*)out)[(size_t)row * 32 + jc] = make_float4(o[0], o[1], o[2], o[3]);
            }
        }
        __syncthreads();
    }
}

// ---------------- fused edge phase: warp per node, pass1-shaped groups -------
// Phase A: 4 edges at a time, 8 lanes/edge (pass1's measured-good reduction
//   shape); ex/as/eid buffered in per-warp smem; denom/cnt via smem atomics.
// Phase B: per-edge coeff + S[n].
// Phase C: gather re-reads tf rows (L1-hot, loaded by this warp in phase A).
#define FW 8
__global__ void __launch_bounds__(32 * FW)
k_fused(const float* __restrict__ tf, const float* __restrict__ cemb) {
    __shared__ float4 emb_s[CC * 32];           // 4KB
    __shared__ float s_ex[FW][FCAP];
    __shared__ float s_cf[FW][FCAP];
    __shared__ int   s_as[FW][FCAP];
    __shared__ int   s_eid[FW][FCAP];
    __shared__ float s_den[FW][CC];
    __shared__ int   s_cnt[FW][CC];

    int tid = threadIdx.x;
    int warp = tid >> 5;
    int lane = tid & 31;
    int sub = lane >> 3;   // 0..3 edge-within-chunk
    int l = lane & 7;      // 0..7 lane-within-edge

    for (int i = tid; i < CC * 32; i += 32 * FW)
        emb_s[i] = ((const float4*)cemb)[i];
    if (lane < CC) { s_den[warp][lane] = 0.f; s_cnt[warp][lane] = 0; }
    __syncthreads();

    int n = blockIdx.x * FW + warp;
    if (n >= NN) return;

    int beg = __ldg(&g_rowptr[n]);
    int deg = __ldg(&g_rowptr[n + 1]) - beg;
    float qbn = __ldg(&g_qb[n]);
    float4 q4[4];
#pragma unroll
    for (int u = 0; u < 4; u++)
        q4[u] = __ldg(&((const float4*)g_qp)[(size_t)n * 32 + u * 8 + l]);

    unsigned used = 0;

    // ---- Phase A ----
    for (int k0 = 0; k0 < deg; k0 += 4) {
        int k = k0 + sub;
        bool on = k < deg;
        int eid = 0;
        float4 t4[4];
#pragma unroll
        for (int u = 0; u < 4; u++) t4[u] = make_float4(0.f, 0.f, 0.f, 0.f);
        if (on) {
            eid = __ldg(&g_eids[beg + k]);
#pragma unroll
            for (int u = 0; u < 4; u++)
                t4[u] = __ldg(&((const float4*)tf)[(size_t)eid * 32 + u * 8 + l]);
        }

        float p[CC + 1];
#pragma unroll
        for (int c = 0; c < CC; c++) {
            float acc = 0.f;
#pragma unroll
            for (int u = 0; u < 4; u++) acc += dot4(t4[u], emb_s[c * 32 + u * 8 + l]);
            p[c] = acc;
        }
        {
            float acc = 0.f;
#pragma unroll
            for (int u = 0; u < 4; u++) acc += dot4(t4[u], q4[u]);
            p[CC] = acc;
        }
#pragma unroll
        for (int v = 0; v <= CC; v++) {
#pragma unroll
            for (int off = 4; off; off >>= 1)
                p[v] += __shfl_xor_sync(0xffffffffu, p[v], off);
        }

        if (on && l == 0) {
            int best = 0; float bvv = p[0];
#pragma unroll
            for (int c = 1; c < CC; c++) if (p[c] > bvv) { bvv = p[c]; best = c; }
            float ex = __expf((p[CC] + qbn) * SCALEF);
            if (k < FCAP) { s_ex[warp][k] = ex; s_as[warp][k] = best; s_eid[warp][k] = eid; }
            else          { g_exo[beg + k] = ex; g_aso[beg + k] = best; }
            atomicAdd(&s_den[warp][best], ex);
            atomicAdd(&s_cnt[warp][best], 1);
            used |= 1u << best;
        }
    }
    __syncwarp();

    if (l == 0 && used) {
#pragma unroll
        for (int c = 0; c < CC; c++)
            if ((used >> c) & 1) g_cflag[c] = 1;   // idempotent
    }

    // ---- Phase B: coefficients + S[n] ----
    float sSum = 0.f;
    for (int k = lane; k < deg; k += 32) {
        float ex; int a;
        if (k < FCAP) { ex = s_ex[warp][k]; a = s_as[warp][k]; }
        else          { ex = g_exo[beg + k]; a = g_aso[beg + k]; }
        float cf = ex / (s_den[warp][a] * (float)s_cnt[warp][a]);
        if (k < FCAP) s_cf[warp][k] = cf;
        else          g_exo[beg + k] = cf;    // reuse slot as coeff
        sSum += cf;
    }
    __syncwarp();
#pragma unroll
    for (int off = 16; off; off >>= 1) sSum += __shfl_xor_sync(0xffffffffu, sSum, off);
    if (lane == 0) g_S[n] = sSum;

    // ---- Phase C: weighted gather (tf rows L1-hot) ----
    float4 acc = make_float4(0.f, 0.f, 0.f, 0.f);
    for (int k0 = 0; k0 < deg; k0 += 4) {
        int m = deg - k0; if (m > 4) m = 4;
        int e4[4]; float c4[4];
#pragma unroll
        for (int u = 0; u < 4; u++) {
            if (u < m) {
                int k = k0 + u;
                if (k < FCAP) { e4[u] = s_eid[warp][k]; c4[u] = s_cf[warp][k]; }
                else { e4[u] = __ldg(&g_eids[beg + k]); c4[u] = g_exo[beg + k]; }
            }
        }
        float4 tv[4];
#pragma unroll
        for (int u = 0; u < 4; u++)
            if (u < m) tv[u] = __ldg(&((const float4*)tf)[(size_t)e4[u] * 32 + lane]);
#pragma unroll
        for (int u = 0; u < 4; u++) {
            if (u >= m) break;
            acc.x += c4[u] * tv[u].x; acc.y += c4[u] * tv[u].y;
            acc.z += c4[u] * tv[u].z; acc.w += c4[u] * tv[u].w;
        }
    }
    ((float4*)g_U)[(size_t)n * 32 + lane] = acc;
}

// ---------------- launch ----------------
extern "C" void kernel_launch(void* const* d_in, const int* in_sizes, int n_in,
                              void* d_out, int out_size) {
    const float* node_feat = (const float*)d_in[0];
    const float* time_feat = (const float*)d_in[1];
    const int*   edge_index = (const int*)d_in[3];
    const float* Wq = (const float*)d_in[4];
    const float* bq = (const float*)d_in[5];
    const float* Wk = (const float*)d_in[6];
    const float* bk = (const float*)d_in[7];
    const float* Wv = (const float*)d_in[8];
    const float* bv = (const float*)d_in[9];
    const float* cemb = (const float*)d_in[10];
    const float* Wo = (const float*)d_in[11];
    const float* bo = (const float*)d_in[12];
    const int* src = edge_index;           // row 0 of [2,E]
    float* out = (float*)d_out;

    void *pWkT, *pWqk, *pWvo, *pbqk, *pbvo, *pqp, *pU, *pS;
    cudaGetSymbolAddress(&pWkT, g_WkT);
    cudaGetSymbolAddress(&pWqk, g_Wqk);
    cudaGetSymbolAddress(&pWvo, g_Wvo);
    cudaGetSymbolAddress(&pbqk, g_bqk);
    cudaGetSymbolAddress(&pbvo, g_bvo);
    cudaGetSymbolAddress(&pqp,  g_qp);
    cudaGetSymbolAddress(&pU,   g_U);
    cudaGetSymbolAddress(&pS,   g_S);

    const int smemGemm = (DD * DD + 64 * DD) * (int)sizeof(float);   // 96 KB
    cudaFuncSetAttribute(k_gemm128, cudaFuncAttributeMaxDynamicSharedMemorySize, smemGemm);

    const int zb = (NN + 127) / 128;
    // slot 4 (profiled) = qp GEMM
    k_prep<<<DD + 1 + zb, 128>>>(Wq, bq, Wk, bk, bv, Wo);                       // 1
    k_gemm128<<<2, 256, smemGemm>>>(Wq, (const float*)pWkT, nullptr, nullptr,   // 2
                                    nullptr, (float*)pWqk, DD, 0, 0, 0);
    k_hist<<<(EE + 255) / 256, 256>>>(src);                                     // 3
    k_gemm128<<<(NN + 63) / 64, 256, smemGemm>>>(node_feat, (const float*)pWqk, // 4 <- profiled
                                                 (const float*)pbqk, nullptr, nullptr,
                                                 (float*)pqp, NN, 0, 1, 0);
    k_scanA<<<NBLK, 256>>>();                                                   // 5
    k_scanB<<<1, 256>>>();                                                      // 6
    k_scanC<<<NBLK, 256>>>();                                                   // 7
    k_scatter<<<(EE + 255) / 256, 256>>>(src);                                  // 8
    k_gemm128<<<2, 256, smemGemm>>>(Wv, Wo, nullptr, nullptr, nullptr,          // 9
                                    (float*)pWvo, DD, 0, 0, 0);
    k_fused<<<(NN + FW - 1) / FW, 32 * FW>>>(time_feat, cemb);                  // 10
    k_gemm128<<<(NN + 63) / 64, 256, smemGemm>>>((const float*)pU,              // 11
                                                 (const float*)pWvo,
                                                 bo, (const float*)pS, (const float*)pbvo,
                                                 out, NN, 1, 0, 1);
}

// round 11
// speedup vs baseline: 1.4128x; 1.4128x over previous
#include <cuda_runtime.h>
#include <math.h>

#define NN 50000
#define EE 600000
#define DD 128
#define CC 8
#define SCALEF 0.08838834764831845f   // 128^-0.5
#define NBLK 196                       // scan blocks: ceil(50000/256)

// ---------------- static device scratch ----------------
__device__ __align__(16) int   g_deg[NN];
__device__ __align__(16) int   g_rowptr[NN + 1];
__device__ __align__(16) int   g_cursor[NN];
__device__ __align__(16) int   g_eids[EE];
__device__ __align__(16) int   g_bsum[NBLK];
__device__ __align__(16) int   g_boff[NBLK];
__device__ __align__(16) float g_WkT[DD * DD];
__device__ __align__(16) float g_Wqk[DD * DD];
__device__ __align__(16) float g_Wvo[DD * DD];
__device__ __align__(16) float g_bqk[DD];
__device__ __align__(16) float g_bvo[DD];
__device__ __align__(16) float g_wqbk[DD];
__device__            float g_bqbk;
__device__ __align__(16) float g_qp[(size_t)NN * DD];
__device__ __align__(16) float g_qb[NN];
__device__ __align__(16) float g_ex[EE];     // exp(attn), CSR order
__device__ __align__(16) int   g_as[EE];     // cluster assign, CSR order
__device__ __align__(16) int   g_cflag[CC];
__device__ __align__(16) float g_U[(size_t)NN * DD];
__device__ __align__(16) float g_S[NN];

// ---------------- packed f32x2 helpers ----------------
__device__ __forceinline__ unsigned long long pack2(float x) {
    unsigned long long r;
    unsigned u = __float_as_uint(x);
    asm("mov.b64 %0, {%1, %1};" : "=l"(r) : "r"(u));
    return r;
}
__device__ __forceinline__ void ffma2(unsigned long long& d, unsigned long long a,
                                      unsigned long long b) {
    asm("fma.rn.f32x2 %0, %1, %2, %0;" : "+l"(d) : "l"(a), "l"(b));
}
__device__ __forceinline__ void unpack2(unsigned long long v, float& lo, float& hi) {
    unsigned a, b;
    asm("mov.b64 {%0, %1}, %2;" : "=r"(a), "=r"(b) : "l"(v));
    lo = __uint_as_float(a); hi = __uint_as_float(b);
}
__device__ __forceinline__ float dot4(float4 a, float4 b) {
    return a.x * b.x + a.y * b.y + a.z * b.z + a.w * b.w;
}

// ---------------- prep + init fused ----------------
__global__ void k_prep(const float* __restrict__ Wq, const float* __restrict__ bq,
                       const float* __restrict__ Wk, const float* __restrict__ bk,
                       const float* __restrict__ bv, const float* __restrict__ Wo) {
    int b = blockIdx.x;
    if (b < DD) {
        int r = b, c = threadIdx.x;
        g_WkT[c * DD + r] = Wk[r * DD + c];
    } else if (b == DD) {
        int j = threadIdx.x;
        float s1 = 0.f, s2 = 0.f, s3 = 0.f;
        for (int l = 0; l < DD; l++) {
            s1 += bq[l] * Wk[j * DD + l];      // bqk  = bq @ Wk^T
            s2 += bv[l] * Wo[l * DD + j];      // bvo  = bv @ Wo
            s3 += Wq[j * DD + l] * bk[l];      // wqbk = Wq @ bk
        }
        g_bqk[j] = s1; g_bvo[j] = s2; g_wqbk[j] = s3;
        if (j < CC) g_cflag[j] = 0;
        if (j == 0) {
            float t = 0.f;
            for (int l = 0; l < DD; l++) t += bq[l] * bk[l];
            g_bqbk = t;
        }
    } else {
        int i = (b - DD - 1) * blockDim.x + threadIdx.x;
        if (i < NN) g_deg[i] = 0;
    }
}

// ---------------- CSR build ----------------
__global__ void k_hist(const int* __restrict__ src) {
    int i = blockIdx.x * blockDim.x + threadIdx.x;
    if (i < EE) atomicAdd(&g_deg[src[i]], 1);
}

__global__ void k_scanA() {
    __shared__ int red[256];
    int i = blockIdx.x * 256 + threadIdx.x;
    int v = (i < NN) ? g_deg[i] : 0;
    red[threadIdx.x] = v;
    __syncthreads();
    for (int off = 128; off; off >>= 1) {
        if (threadIdx.x < off) red[threadIdx.x] += red[threadIdx.x + off];
        __syncthreads();
    }
    if (threadIdx.x == 0) g_bsum[blockIdx.x] = red[0];
}

__global__ void k_scanB() {
    __shared__ int s[256];
    int tid = threadIdx.x;
    int v = (tid < NBLK) ? g_bsum[tid] : 0;
    s[tid] = v;
    __syncthreads();
    for (int off = 1; off < 256; off <<= 1) {
        int t = (tid >= off) ? s[tid - off] : 0;
        __syncthreads();
        s[tid] += t;
        __syncthreads();
    }
    if (tid < NBLK) g_boff[tid] = s[tid] - v;
    if (tid == 255) g_rowptr[NN] = s[255];
}

__global__ void k_scanC() {
    __shared__ int s[256];
    int tid = threadIdx.x;
    int i = blockIdx.x * 256 + tid;
    int v = (i < NN) ? g_deg[i] : 0;
    s[tid] = v;
    __syncthreads();
    for (int off = 1; off < 256; off <<= 1) {
        int t = (tid >= off) ? s[tid - off] : 0;
        __syncthreads();
        s[tid] += t;
        __syncthreads();
    }
    if (i < NN) {
        int e = g_boff[blockIdx.x] + s[tid] - v;
        g_rowptr[i] = e;
        g_cursor[i] = e;
    }
}

__global__ void k_scatter(const int* __restrict__ src) {
    int i = blockIdx.x * blockDim.x + threadIdx.x;
    if (i < EE) {
        int p = atomicAdd(&g_cursor[src[i]], 1);
        g_eids[p] = i;
    }
}

// ---------------- [M,128] @ [128,128] GEMM (R6 shape, measured ~49us) -------
__global__ void __launch_bounds__(256, 2)
k_gemm128(const float* __restrict__ A, const float* __restrict__ W,
          const float* __restrict__ bias, const float* __restrict__ rowscale,
          const float* __restrict__ vecterm, float* __restrict__ out,
          int M, int doRelu, int doQb, int useInvnn) {
    extern __shared__ float smem[];
    float4* Ws4 = (float4*)smem;                 // 128*128 floats (64KB)
    float4* As4 = (float4*)(smem + DD * DD);     // 64*128 floats (32KB)
    const ulonglong2* WsU = (const ulonglong2*)smem;

    for (int i = threadIdx.x; i < DD * DD / 4; i += blockDim.x)
        Ws4[i] = ((const float4*)W)[i];
    __syncthreads();

    int r = threadIdx.x >> 5;    // 0..7 row group (uniform per warp)
    int jc = threadIdx.x & 31;   // 0..31 col group (4 cols)

    float gs = 1.f;
    if (useInvnn) {
        int nn = 0;
#pragma unroll
        for (int c = 0; c < CC; c++) nn += g_cflag[c];
        if (nn < 1) nn = 1;
        gs = 1.f / (float)nn;
    }

    for (int tile = blockIdx.x; tile * 64 < M; tile += gridDim.x) {
        int row0 = tile * 64;
        for (int i = threadIdx.x; i < 64 * 32; i += blockDim.x) {
            int rr = i >> 5, cc = i & 31;
            float4 v = make_float4(0.f, 0.f, 0.f, 0.f);
            if (row0 + rr < M) v = ((const float4*)A)[(size_t)(row0 + rr) * 32 + cc];
            As4[i] = v;
        }
        __syncthreads();

        unsigned long long acc2[8][2];
#pragma unroll
        for (int a = 0; a < 8; a++) { acc2[a][0] = 0ull; acc2[a][1] = 0ull; }

#pragma unroll 2
        for (int k4 = 0; k4 < 32; k4++) {
            float4 a4[8];
#pragma unroll
            for (int rr = 0; rr < 8; rr++) a4[rr] = As4[(r * 8 + rr) * 32 + k4];  // broadcast
#pragma unroll
            for (int kk = 0; kk < 4; kk++) {
                int k = k4 * 4 + kk;
                ulonglong2 w = WsU[k * 32 + jc];
#pragma unroll
                for (int rr = 0; rr < 8; rr++) {
                    float av = (kk == 0) ? a4[rr].x : (kk == 1) ? a4[rr].y
                             : (kk == 2) ? a4[rr].z : a4[rr].w;
                    unsigned long long av2 = pack2(av);
                    ffma2(acc2[rr][0], av2, w.x);
                    ffma2(acc2[rr][1], av2, w.y);
                }
            }
        }

        if (doQb) {
            float4 wq = ((const float4*)g_wqbk)[jc];
#pragma unroll
            for (int rr = 0; rr < 8; rr++) {
                int row = row0 + r * 8 + rr;
                float4 a0 = As4[(r * 8 + rr) * 32 + jc];
                float part = dot4(a0, wq);
#pragma unroll
                for (int off = 16; off; off >>= 1)
                    part += __shfl_xor_sync(0xffffffffu, part, off);
                if (jc == 0 && row < M) g_qb[row] = part + g_bqbk;
            }
        }

        float bv4[4] = {0,0,0,0}, vv4[4] = {0,0,0,0};
        if (bias) {
            float4 b0 = ((const float4*)bias)[jc];
            bv4[0]=b0.x; bv4[1]=b0.y; bv4[2]=b0.z; bv4[3]=b0.w;
        }
        if (vecterm) {
            float4 v0 = ((const float4*)vecterm)[jc];
            vv4[0]=v0.x; vv4[1]=v0.y; vv4[2]=v0.z; vv4[3]=v0.w;
        }

#pragma unroll
        for (int rr = 0; rr < 8; rr++) {
            int row = row0 + r * 8 + rr;
            if (row < M) {
                float sc = rowscale ? rowscale[row] : 0.f;
                float o[4];
                unpack2(acc2[rr][0], o[0], o[1]);
                unpack2(acc2[rr][1], o[2], o[3]);
#pragma unroll
                for (int c = 0; c < 4; c++) {
                    o[c] = gs * (o[c] + sc * vv4[c]) + bv4[c];
                    if (doRelu) o[c] = fmaxf(o[c], 0.f);
                }
                ((float4*)out)[(size_t)row * 32 + jc] = make_float4(o[0], o[1], o[2], o[3]);
            }
        }
        __syncthreads();
    }
}

// ---------------- pass1: CSR-ordered, 4 lanes/edge, 8 edges/warp ----------------
// 2 shuffle levels instead of 3; 8 tf rows in flight per warp.
__global__ void __launch_bounds__(256) k_pass1(const float* __restrict__ tf,
                                               const int* __restrict__ src,
                                               const float* __restrict__ cemb) {
    __shared__ float4 emb_s[CC * 32];
    __shared__ int s_f[CC];
    if (threadIdx.x < CC) s_f[threadIdx.x] = 0;
    for (int i = threadIdx.x; i < CC * 32; i += blockDim.x)
        emb_s[i] = ((const float4*)cemb)[i];
    __syncthreads();

    int gw = (blockIdx.x * blockDim.x + threadIdx.x) >> 5;
    int lane = threadIdx.x & 31;
    int sub = lane >> 2;   // 0..7 edge-within-warp
    int l = lane & 3;      // 0..3 lane-within-edge
    int i = gw * 8 + sub;  // CSR slot; grid exact (EE % 64 == 0)
    int e = __ldg(&g_eids[i]);
    int s = __ldg(&src[e]);

    float4 t4[8];
#pragma unroll
    for (int u = 0; u < 8; u++)
        t4[u] = __ldg(&((const float4*)tf)[(size_t)e * 32 + u * 4 + l]);

    float p[CC + 1];
    {
        float acc = 0.f;
#pragma unroll
        for (int u = 0; u < 8; u++)
            acc += dot4(t4[u], __ldg(&((const float4*)g_qp)[(size_t)s * 32 + u * 4 + l]));
        p[CC] = acc;
    }
#pragma unroll
    for (int c = 0; c < CC; c++) {
        float acc = 0.f;
#pragma unroll
        for (int u = 0; u < 8; u++) acc += dot4(t4[u], emb_s[c * 32 + u * 4 + l]);
        p[c] = acc;
    }

#pragma unroll
    for (int v = 0; v <= CC; v++) {
#pragma unroll
        for (int off = 2; off; off >>= 1)
            p[v] += __shfl_xor_sync(0xffffffffu, p[v], off);
    }

    if (l == 0) {
        int best = 0; float bvv = p[0];
#pragma unroll
        for (int c = 1; c < CC; c++) if (p[c] > bvv) { bvv = p[c]; best = c; }
        float ex = __expf((p[CC] + __ldg(&g_qb[s])) * SCALEF);
        g_ex[i] = ex;
        g_as[i] = best;
        s_f[best] = 1;
    }
    __syncthreads();
    if (threadIdx.x < CC && s_f[threadIdx.x]) g_cflag[threadIdx.x] = 1;
}

// ---------------- pass2: 2 warps per node (split-D), float2 per lane ---------
// Each warp of a pair owns 64 of 128 dims; denom/cnt computed redundantly
// per warp (12 extra tiny loads — cheap). 100k warps of latency-bound gather.
#define P2_WPB 8   // warps per block => 4 nodes per block
__global__ void __launch_bounds__(32 * P2_WPB) k_pass2(const float* __restrict__ tf) {
    __shared__ float s_den[P2_WPB][CC];
    __shared__ int   s_cnt[P2_WPB][CC];

    int warp = threadIdx.x >> 5;
    int lane = threadIdx.x & 31;
    int pairid = warp >> 1;
    int half = warp & 1;
    int n = blockIdx.x * (P2_WPB / 2) + pairid;
    if (n >= NN) return;

    if (lane < CC) { s_den[warp][lane] = 0.f; s_cnt[warp][lane] = 0; }
    __syncwarp();

    int beg = __ldg(&g_rowptr[n]);
    int deg = __ldg(&g_rowptr[n + 1]) - beg;
    int rounds = (deg + 31) >> 5;

    float2 acc = make_float2(0.f, 0.f);
    float sSum = 0.f;

    for (int r0 = 0; r0 < rounds; r0++) {
        int k = r0 * 32 + lane;
        bool on = k < deg;
        float ex = 0.f; int a = 0, eid = 0;
        if (on) {
            ex  = __ldg(&g_ex[beg + k]);
            a   = __ldg(&g_as[beg + k]);
            eid = __ldg(&g_eids[beg + k]);
            atomicAdd(&s_den[warp][a], ex);
            atomicAdd(&s_cnt[warp][a], 1);
        }
        __syncwarp();
        float cf = 0.f;
        if (on) cf = ex / (s_den[warp][a] * (float)s_cnt[warp][a]);
        if (rounds == 1) {
            sSum += cf;
            int cnt = deg;
#pragma unroll 4
            for (int kk = 0; kk < 32; kk++) {
                if (kk >= cnt) break;
                float c  = __shfl_sync(0xffffffffu, cf, kk);
                int   ee = __shfl_sync(0xffffffffu, eid, kk);
                float2 tv = __ldg(&((const float2*)tf)[(size_t)ee * 64 + half * 32 + lane]);
                acc.x += c * tv.x; acc.y += c * tv.y;
            }
        }
    }

    if (rounds > 1) {
        __syncwarp();
        for (int r0 = 0; r0 < rounds; r0++) {
            int k = r0 * 32 + lane;
            bool on = k < deg;
            float cf = 0.f; int eid = 0;
            if (on) {
                float ex = __ldg(&g_ex[beg + k]);
                int a = __ldg(&g_as[beg + k]);
                eid = __ldg(&g_eids[beg + k]);
                cf = ex / (s_den[warp][a] * (float)s_cnt[warp][a]);
            }
            sSum += cf;
            int cnt = deg - r0 * 32; if (cnt > 32) cnt = 32;
            for (int kk = 0; kk < cnt; kk++) {
                float c  = __shfl_sync(0xffffffffu, cf, kk);
                int   ee = __shfl_sync(0xffffffffu, eid, kk);
                float2 tv = __ldg(&((const float2*)tf)[(size_t)ee * 64 + half * 32 + lane]);
                acc.x += c * tv.x; acc.y += c * tv.y;
            }
        }
    }

    ((float2*)g_U)[(size_t)n * 64 + half * 32 + lane] = acc;

    if (half == 0) {
#pragma unroll
        for (int off = 16; off; off >>= 1) sSum += __shfl_xor_sync(0xffffffffu, sSum, off);
        if (lane == 0) g_S[n] = sSum;
    }
}

// ---------------- launch ----------------
extern "C" void kernel_launch(void* const* d_in, const int* in_sizes, int n_in,
                              void* d_out, int out_size) {
    const float* node_feat = (const float*)d_in[0];
    const float* time_feat = (const float*)d_in[1];
    const int*   edge_index = (const int*)d_in[3];
    const float* Wq = (const float*)d_in[4];
    const float* bq = (const float*)d_in[5];
    const float* Wk = (const float*)d_in[6];
    const float* bk = (const float*)d_in[7];
    const float* Wv = (const float*)d_in[8];
    const float* bv = (const float*)d_in[9];
    const float* cemb = (const float*)d_in[10];
    const float* Wo = (const float*)d_in[11];
    const float* bo = (const float*)d_in[12];
    const int* src = edge_index;           // row 0 of [2,E]
    float* out = (float*)d_out;

    void *pWkT, *pWqk, *pWvo, *pbqk, *pbvo, *pqp, *pU, *pS;
    cudaGetSymbolAddress(&pWkT, g_WkT);
    cudaGetSymbolAddress(&pWqk, g_Wqk);
    cudaGetSymbolAddress(&pWvo, g_Wvo);
    cudaGetSymbolAddress(&pbqk, g_bqk);
    cudaGetSymbolAddress(&pbvo, g_bvo);
    cudaGetSymbolAddress(&pqp,  g_qp);
    cudaGetSymbolAddress(&pU,   g_U);
    cudaGetSymbolAddress(&pS,   g_S);

    const int smemGemm = (DD * DD + 64 * DD) * (int)sizeof(float);   // 96 KB
    cudaFuncSetAttribute(k_gemm128, cudaFuncAttributeMaxDynamicSharedMemorySize, smemGemm);

    const int zb = (NN + 127) / 128;
    // slot 4 (profiled) = qp GEMM
    k_prep<<<DD + 1 + zb, 128>>>(Wq, bq, Wk, bk, bv, Wo);                       // 1
    k_gemm128<<<2, 256, smemGemm>>>(Wq, (const float*)pWkT, nullptr, nullptr,   // 2
                                    nullptr, (float*)pWqk, DD, 0, 0, 0);
    k_hist<<<(EE + 255) / 256, 256>>>(src);                                     // 3
    k_gemm128<<<(NN + 63) / 64, 256, smemGemm>>>(node_feat, (const float*)pWqk, // 4 <- profiled
                                                 (const float*)pbqk, nullptr, nullptr,
                                                 (float*)pqp, NN, 0, 1, 0);
    k_scanA<<<NBLK, 256>>>();                                                   // 5
    k_scanB<<<1, 256>>>();                                                      // 6
    k_scanC<<<NBLK, 256>>>();                                                   // 7
    k_scatter<<<(EE + 255) / 256, 256>>>(src);                                  // 8
    k_gemm128<<<2, 256, smemGemm>>>(Wv, Wo, nullptr, nullptr, nullptr,          // 9
                                    (float*)pWvo, DD, 0, 0, 0);
    k_pass1<<<EE / 64, 256>>>(time_feat, src, cemb);                            // 10
    k_pass2<<<(NN * 2 + P2_WPB - 1) / P2_WPB, 32 * P2_WPB>>>(time_feat);        // 11
    k_gemm128<<<(NN + 63) / 64, 256, smemGemm>>>((const float*)pU,              // 12
                                                 (const float*)pWvo,
                                                 bo, (const float*)pS, (const float*)pbvo,
                                                 out, NN, 1, 0, 1);
}

// round 12
// speedup vs baseline: 1.4849x; 1.0511x over previous
#include <cuda_runtime.h>
#include <math.h>

#define NN 50000
#define EE 600000
#define DD 128
#define CC 8
#define SCALEF 0.08838834764831845f   // 128^-0.5
#define NBLK 196                       // scan blocks: ceil(50000/256)
#define QPTILES 782                    // ceil(50000/64)

// ---------------- static device scratch ----------------
__device__ __align__(16) int   g_deg[NN];
__device__ __align__(16) int   g_rowptr[NN + 1];
__device__ __align__(16) int   g_cursor[NN];
__device__ __align__(16) int   g_eids[EE];
__device__ __align__(16) int   g_bsum[NBLK];
__device__ __align__(16) float g_WkT[DD * DD];
__device__ __align__(16) float g_Wqk[DD * DD];
__device__ __align__(16) float g_Wvo[DD * DD];
__device__ __align__(16) float g_bqk[DD];
__device__ __align__(16) float g_bvo[DD];
__device__ __align__(16) float g_wqbk[DD];
__device__            float g_bqbk;
__device__ __align__(16) float g_qp[(size_t)NN * DD];
__device__ __align__(16) float g_qb[NN];
__device__ __align__(16) float g_ex[EE];     // exp(attn), EDGE order
__device__ __align__(16) int   g_as[EE];     // cluster assign, EDGE order
__device__ __align__(16) int   g_cflag[CC];
__device__ __align__(16) float g_U[(size_t)NN * DD];
__device__ __align__(16) float g_S[NN];

// ---------------- packed f32x2 helpers ----------------
__device__ __forceinline__ unsigned long long pack2(float x) {
    unsigned long long r;
    unsigned u = __float_as_uint(x);
    asm("mov.b64 %0, {%1, %1};" : "=l"(r) : "r"(u));
    return r;
}
__device__ __forceinline__ void ffma2(unsigned long long& d, unsigned long long a,
                                      unsigned long long b) {
    asm("fma.rn.f32x2 %0, %1, %2, %0;" : "+l"(d) : "l"(a), "l"(b));
}
__device__ __forceinline__ void unpack2(unsigned long long v, float& lo, float& hi) {
    unsigned a, b;
    asm("mov.b64 {%0, %1}, %2;" : "=r"(a), "=r"(b) : "l"(v));
    lo = __uint_as_float(a); hi = __uint_as_float(b);
}
__device__ __forceinline__ float dot4(float4 a, float4 b) {
    return a.x * b.x + a.y * b.y + a.z * b.z + a.w * b.w;
}

// ---------------- prep + init fused ----------------
__global__ void k_prep(const float* __restrict__ Wq, const float* __restrict__ bq,
                       const float* __restrict__ Wk, const float* __restrict__ bk,
                       const float* __restrict__ bv, const float* __restrict__ Wo) {
    int b = blockIdx.x;
    if (b < DD) {
        int r = b, c = threadIdx.x;
        g_WkT[c * DD + r] = Wk[r * DD + c];
    } else if (b == DD) {
        int j = threadIdx.x;
        float s1 = 0.f, s2 = 0.f, s3 = 0.f;
        for (int l = 0; l < DD; l++) {
            s1 += bq[l] * Wk[j * DD + l];      // bqk  = bq @ Wk^T
            s2 += bv[l] * Wo[l * DD + j];      // bvo  = bv @ Wo
            s3 += Wq[j * DD + l] * bk[l];      // wqbk = Wq @ bk
        }
        g_bqk[j] = s1; g_bvo[j] = s2; g_wqbk[j] = s3;
        if (j < CC) g_cflag[j] = 0;
        if (j == 0) {
            float t = 0.f;
            for (int l = 0; l < DD; l++) t += bq[l] * bk[l];
            g_bqbk = t;
        }
    } else {
        int i = (b - DD - 1) * blockDim.x + threadIdx.x;
        if (i < NN) g_deg[i] = 0;
    }
}

// ---------------- shared GEMM tile helpers (64 rows x 128 cols, 256 thr) ----
__device__ __forceinline__ void dgemm_weight(const float* __restrict__ A,
                                             const float* __restrict__ W,
                                             float* __restrict__ out, int tile) {
    extern __shared__ float smem[];
    float4* Ws4 = (float4*)smem;
    float4* As4 = (float4*)(smem + DD * DD);
    const ulonglong2* WsU = (const ulonglong2*)smem;

    for (int i = threadIdx.x; i < DD * DD / 4; i += 256)
        Ws4[i] = ((const float4*)W)[i];
    int row0 = tile * 64;
    for (int i = threadIdx.x; i < 64 * 32; i += 256) {
        int rr = i >> 5, cc = i & 31;
        As4[i] = ((const float4*)A)[(size_t)(row0 + rr) * 32 + cc];
    }
    __syncthreads();

    int r = threadIdx.x >> 5;
    int jc = threadIdx.x & 31;

    unsigned long long acc2[8][2];
#pragma unroll
    for (int a = 0; a < 8; a++) { acc2[a][0] = 0ull; acc2[a][1] = 0ull; }

#pragma unroll 2
    for (int k4 = 0; k4 < 32; k4++) {
        float4 a4[8];
#pragma unroll
        for (int rr = 0; rr < 8; rr++) a4[rr] = As4[(r * 8 + rr) * 32 + k4];
#pragma unroll
        for (int kk = 0; kk < 4; kk++) {
            int k = k4 * 4 + kk;
            ulonglong2 w = WsU[k * 32 + jc];
#pragma unroll
            for (int rr = 0; rr < 8; rr++) {
                float av = (kk == 0) ? a4[rr].x : (kk == 1) ? a4[rr].y
                         : (kk == 2) ? a4[rr].z : a4[rr].w;
                unsigned long long av2 = pack2(av);
                ffma2(acc2[rr][0], av2, w.x);
                ffma2(acc2[rr][1], av2, w.y);
            }
        }
    }
#pragma unroll
    for (int rr = 0; rr < 8; rr++) {
        int row = row0 + r * 8 + rr;
        float o[4];
        unpack2(acc2[rr][0], o[0], o[1]);
        unpack2(acc2[rr][1], o[2], o[3]);
        ((float4*)out)[(size_t)row * 32 + jc] = make_float4(o[0], o[1], o[2], o[3]);
    }
}

__device__ __forceinline__ void dgemm_qp(const float* __restrict__ A, int tile) {
    extern __shared__ float smem[];
    float4* Ws4 = (float4*)smem;
    float4* As4 = (float4*)(smem + DD * DD);
    const ulonglong2* WsU = (const ulonglong2*)smem;

    for (int i = threadIdx.x; i < DD * DD / 4; i += 256)
        Ws4[i] = ((const float4*)g_Wqk)[i];
    int row0 = tile * 64;
    for (int i = threadIdx.x; i < 64 * 32; i += 256) {
        int rr = i >> 5, cc = i & 31;
        float4 v = make_float4(0.f, 0.f, 0.f, 0.f);
        if (row0 + rr < NN) v = ((const float4*)A)[(size_t)(row0 + rr) * 32 + cc];
        As4[i] = v;
    }
    __syncthreads();

    int r = threadIdx.x >> 5;
    int jc = threadIdx.x & 31;

    unsigned long long acc2[8][2];
#pragma unroll
    for (int a = 0; a < 8; a++) { acc2[a][0] = 0ull; acc2[a][1] = 0ull; }

#pragma unroll 2
    for (int k4 = 0; k4 < 32; k4++) {
        float4 a4[8];
#pragma unroll
        for (int rr = 0; rr < 8; rr++) a4[rr] = As4[(r * 8 + rr) * 32 + k4];
#pragma unroll
        for (int kk = 0; kk < 4; kk++) {
            int k = k4 * 4 + kk;
            ulonglong2 w = WsU[k * 32 + jc];
#pragma unroll
            for (int rr = 0; rr < 8; rr++) {
                float av = (kk == 0) ? a4[rr].x : (kk == 1) ? a4[rr].y
                         : (kk == 2) ? a4[rr].z : a4[rr].w;
                unsigned long long av2 = pack2(av);
                ffma2(acc2[rr][0], av2, w.x);
                ffma2(acc2[rr][1], av2, w.y);
            }
        }
    }

    // fused qb epilogue
    {
        float4 wq = ((const float4*)g_wqbk)[jc];
#pragma unroll
        for (int rr = 0; rr < 8; rr++) {
            int row = row0 + r * 8 + rr;
            float4 a0 = As4[(r * 8 + rr) * 32 + jc];
            float part = dot4(a0, wq);
#pragma unroll
            for (int off = 16; off; off >>= 1)
                part += __shfl_xor_sync(0xffffffffu, part, off);
            if (jc == 0 && row < NN) g_qb[row] = part + g_bqbk;
        }
    }

    float4 b0 = ((const float4*)g_bqk)[jc];
#pragma unroll
    for (int rr = 0; rr < 8; rr++) {
        int row = row0 + r * 8 + rr;
        if (row < NN) {
            float o[4];
            unpack2(acc2[rr][0], o[0], o[1]);
            unpack2(acc2[rr][1], o[2], o[3]);
            o[0] += b0.x; o[1] += b0.y; o[2] += b0.z; o[3] += b0.w;
            ((float4*)g_qp)[(size_t)row * 32 + jc] = make_float4(o[0], o[1], o[2], o[3]);
        }
    }
}

// ---------------- combo1: weight GEMMs + histogram ----------------
__global__ void __launch_bounds__(256, 2)
k_combo1(const float* __restrict__ Wq, const float* __restrict__ Wv,
         const float* __restrict__ Wo, const int* __restrict__ src) {
    if (blockIdx.x < 2) {
        dgemm_weight(Wq, g_WkT, g_Wqk, blockIdx.x);
    } else if (blockIdx.x < 4) {
        dgemm_weight(Wv, Wo, g_Wvo, blockIdx.x - 2);
    } else {
        int i = (blockIdx.x - 4) * 256 + threadIdx.x;
        if (i < EE) atomicAdd(&g_deg[src[i]], 1);
    }
}

// ---------------- combo2: qp GEMM + scanA ----------------
__global__ void __launch_bounds__(256, 2)
k_combo2(const float* __restrict__ nf) {
    if (blockIdx.x < QPTILES) {
        dgemm_qp(nf, blockIdx.x);
    } else {
        __shared__ int red[256];
        int sb = blockIdx.x - QPTILES;
        int i = sb * 256 + threadIdx.x;
        int v = (i < NN) ? g_deg[i] : 0;
        red[threadIdx.x] = v;
        __syncthreads();
        for (int off = 128; off; off >>= 1) {
            if (threadIdx.x < off) red[threadIdx.x] += red[threadIdx.x + off];
            __syncthreads();
        }
        if (threadIdx.x == 0) g_bsum[sb] = red[0];
    }
}

// ---------------- scanC2: per-block offset from bsum + local scan ----------
__global__ void k_scanC2() {
    __shared__ int s[256];
    __shared__ int s2[256];
    int tid = threadIdx.x, bid = blockIdx.x;
    int v = (tid < bid) ? g_bsum[tid] : 0;
    s2[tid] = v;
    __syncthreads();
    for (int off = 128; off; off >>= 1) {
        if (tid < off) s2[tid] += s2[tid + off];
        __syncthreads();
    }
    int base = s2[0];

    int i = bid * 256 + tid;
    int d = (i < NN) ? g_deg[i] : 0;
    s[tid] = d;
    __syncthreads();
    for (int off = 1; off < 256; off <<= 1) {
        int t = (tid >= off) ? s[tid - off] : 0;
        __syncthreads();
        s[tid] += t;
        __syncthreads();
    }
    if (i < NN) {
        int e = base + s[tid] - d;
        g_rowptr[i] = e;
        g_cursor[i] = e;
    }
    if (bid == NBLK - 1 && tid == 255) g_rowptr[NN] = base + s[255];
}

__global__ void k_scatter(const int* __restrict__ src) {
    int i = blockIdx.x * blockDim.x + threadIdx.x;
    if (i < EE) {
        int p = atomicAdd(&g_cursor[src[i]], 1);
        g_eids[p] = i;
    }
}

// ---------------- pass1: EDGE-ordered, 8 lanes/edge, 4 edges/warp -----------
__global__ void __launch_bounds__(256) k_pass1(const float* __restrict__ tf,
                                               const int* __restrict__ src,
                                               const float* __restrict__ cemb) {
    __shared__ float4 emb_s[CC * 32];
    __shared__ int s_f[CC];
    if (threadIdx.x < CC) s_f[threadIdx.x] = 0;
    for (int i = threadIdx.x; i < CC * 32; i += blockDim.x)
        emb_s[i] = ((const float4*)cemb)[i];
    __syncthreads();

    int gw = (blockIdx.x * blockDim.x + threadIdx.x) >> 5;
    int lane = threadIdx.x & 31;
    int sub = lane >> 3;
    int l = lane & 7;
    int e = gw * 4 + sub;          // edge id; grid exact, e < EE
    int s = __ldg(&src[e]);

    float4 t4[4], q4[4];
#pragma unroll
    for (int u = 0; u < 4; u++) {
        t4[u] = __ldg(&((const float4*)tf)[(size_t)e * 32 + u * 8 + l]);
        q4[u] = __ldg(&((const float4*)g_qp)[(size_t)s * 32 + u * 8 + l]);
    }

    float p[CC + 1];
#pragma unroll
    for (int c = 0; c < CC; c++) {
        float acc = 0.f;
#pragma unroll
        for (int u = 0; u < 4; u++) acc += dot4(t4[u], emb_s[c * 32 + u * 8 + l]);
        p[c] = acc;
    }
    {
        float acc = 0.f;
#pragma unroll
        for (int u = 0; u < 4; u++) acc += dot4(t4[u], q4[u]);
        p[CC] = acc;
    }

#pragma unroll
    for (int v = 0; v <= CC; v++) {
#pragma unroll
        for (int off = 4; off; off >>= 1)
            p[v] += __shfl_xor_sync(0xffffffffu, p[v], off);
    }

    if (l == 0) {
        int best = 0; float bvv = p[0];
#pragma unroll
        for (int c = 1; c < CC; c++) if (p[c] > bvv) { bvv = p[c]; best = c; }
        float ex = __expf((p[CC] + __ldg(&g_qb[s])) * SCALEF);
        g_ex[e] = ex;
        g_as[e] = best;
        s_f[best] = 1;
    }
    __syncthreads();
    if (threadIdx.x < CC && s_f[threadIdx.x]) g_cflag[threadIdx.x] = 1;
}

// ---------------- pass2: WARP per node (R9 shape; ex/as gathered via eid) ---
#define P2_WPB 8
__global__ void __launch_bounds__(32 * P2_WPB) k_pass2(const float* __restrict__ tf) {
    __shared__ float s_den[P2_WPB][CC];
    __shared__ int   s_cnt[P2_WPB][CC];

    int warp = threadIdx.x >> 5;
    int lane = threadIdx.x & 31;
    int n = blockIdx.x * P2_WPB + warp;
    if (n >= NN) return;

    if (lane < CC) { s_den[warp][lane] = 0.f; s_cnt[warp][lane] = 0; }
    __syncwarp();

    int beg = __ldg(&g_rowptr[n]);
    int deg = __ldg(&g_rowptr[n + 1]) - beg;
    int rounds = (deg + 31) >> 5;

    float4 acc = make_float4(0.f, 0.f, 0.f, 0.f);
    float sSum = 0.f;

    for (int r0 = 0; r0 < rounds; r0++) {
        int k = r0 * 32 + lane;
        bool on = k < deg;
        float ex = 0.f; int a = 0, eid = 0;
        if (on) {
            eid = __ldg(&g_eids[beg + k]);
            ex  = __ldg(&g_ex[eid]);
            a   = __ldg(&g_as[eid]);
            atomicAdd(&s_den[warp][a], ex);
            atomicAdd(&s_cnt[warp][a], 1);
        }
        __syncwarp();
        float cf = 0.f;
        if (on) cf = ex / (s_den[warp][a] * (float)s_cnt[warp][a]);
        if (rounds == 1) {
            sSum += cf;
            int cnt = deg;
#pragma unroll 4
            for (int kk = 0; kk < 32; kk++) {
                if (kk >= cnt) break;
                float c  = __shfl_sync(0xffffffffu, cf, kk);
                int   ee = __shfl_sync(0xffffffffu, eid, kk);
                float4 tv = __ldg(&((const float4*)tf)[(size_t)ee * 32 + lane]);
                acc.x += c * tv.x; acc.y += c * tv.y;
                acc.z += c * tv.z; acc.w += c * tv.w;
            }
        }
    }

    if (rounds > 1) {
        __syncwarp();
        for (int r0 = 0; r0 < rounds; r0++) {
            int k = r0 * 32 + lane;
            bool on = k < deg;
            float cf = 0.f; int eid = 0;
            if (on) {
                eid = __ldg(&g_eids[beg + k]);
                float ex = __ldg(&g_ex[eid]);
                int a = __ldg(&g_as[eid]);
                cf = ex / (s_den[warp][a] * (float)s_cnt[warp][a]);
            }
            sSum += cf;
            int cnt = deg - r0 * 32; if (cnt > 32) cnt = 32;
            for (int kk = 0; kk < cnt; kk++) {
                float c  = __shfl_sync(0xffffffffu, cf, kk);
                int   ee = __shfl_sync(0xffffffffu, eid, kk);
                float4 tv = __ldg(&((const float4*)tf)[(size_t)ee * 32 + lane]);
                acc.x += c * tv.x; acc.y += c * tv.y;
                acc.z += c * tv.z; acc.w += c * tv.w;
            }
        }
    }

    ((float4*)g_U)[(size_t)n * 32 + lane] = acc;

#pragma unroll
    for (int off = 16; off; off >>= 1) sSum += __shfl_xor_sync(0xffffffffu, sSum, off);
    if (lane == 0) g_S[n] = sSum;
}

// ---------------- final GEMM: out = relu(invnn*(U@Wvo + S*bvo) + bo) --------
__global__ void __launch_bounds__(256, 2)
k_gemm_final(const float* __restrict__ A, const float* __restrict__ bo,
             float* __restrict__ out) {
    extern __shared__ float smem[];
    float4* Ws4 = (float4*)smem;
    float4* As4 = (float4*)(smem + DD * DD);
    const ulonglong2* WsU = (const ulonglong2*)smem;

    for (int i = threadIdx.x; i < DD * DD / 4; i += 256)
        Ws4[i] = ((const float4*)g_Wvo)[i];
    __syncthreads();

    int r = threadIdx.x >> 5;
    int jc = threadIdx.x & 31;

    int nn = 0;
#pragma unroll
    for (int c = 0; c < CC; c++) nn += g_cflag[c];
    if (nn < 1) nn = 1;
    float gs = 1.f / (float)nn;

    int row0 = blockIdx.x * 64;
    for (int i = threadIdx.x; i < 64 * 32; i += 256) {
        int rr = i >> 5, cc = i & 31;
        float4 v = make_float4(0.f, 0.f, 0.f, 0.f);
        if (row0 + rr < NN) v = ((const float4*)A)[(size_t)(row0 + rr) * 32 + cc];
        As4[i] = v;
    }
    __syncthreads();

    unsigned long long acc2[8][2];
#pragma unroll
    for (int a = 0; a < 8; a++) { acc2[a][0] = 0ull; acc2[a][1] = 0ull; }

#pragma unroll 2
    for (int k4 = 0; k4 < 32; k4++) {
        float4 a4[8];
#pragma unroll
        for (int rr = 0; rr < 8; rr++) a4[rr] = As4[(r * 8 + rr) * 32 + k4];
#pragma unroll
        for (int kk = 0; kk < 4; kk++) {
            int k = k4 * 4 + kk;
            ulonglong2 w = WsU[k * 32 + jc];
#pragma unroll
            for (int rr = 0; rr < 8; rr++) {
                float av = (kk == 0) ? a4[rr].x : (kk == 1) ? a4[rr].y
                         : (kk == 2) ? a4[rr].z : a4[rr].w;
                unsigned long long av2 = pack2(av);
                ffma2(acc2[rr][0], av2, w.x);
                ffma2(acc2[rr][1], av2, w.y);
            }
        }
    }

    float4 b0 = ((const float4*)bo)[jc];
    float4 v0 = ((const float4*)g_bvo)[jc];

#pragma unroll
    for (int rr = 0; rr < 8; rr++) {
        int row = row0 + r * 8 + rr;
        if (row < NN) {
            float sc = g_S[row];
            float o[4];
            unpack2(acc2[rr][0], o[0], o[1]);
            unpack2(acc2[rr][1], o[2], o[3]);
            o[0] = fmaxf(gs * (o[0] + sc * v0.x) + b0.x, 0.f);
            o[1] = fmaxf(gs * (o[1] + sc * v0.y) + b0.y, 0.f);
            o[2] = fmaxf(gs * (o[2] + sc * v0.z) + b0.z, 0.f);
            o[3] = fmaxf(gs * (o[3] + sc * v0.w) + b0.w, 0.f);
            ((float4*)out)[(size_t)row * 32 + jc] = make_float4(o[0], o[1], o[2], o[3]);
        }
    }
}

// ---------------- launch ----------------
extern "C" void kernel_launch(void* const* d_in, const int* in_sizes, int n_in,
                              void* d_out, int out_size) {
    const float* node_feat = (const float*)d_in[0];
    const float* time_feat = (const float*)d_in[1];
    const int*   edge_index = (const int*)d_in[3];
    const float* Wq = (const float*)d_in[4];
    const float* bq = (const float*)d_in[5];
    const float* Wk = (const float*)d_in[6];
    const float* bk = (const float*)d_in[7];
    const float* Wv = (const float*)d_in[8];
    const float* bv = (const float*)d_in[9];
    const float* cemb = (const float*)d_in[10];
    const float* Wo = (const float*)d_in[11];
    const float* bo = (const float*)d_in[12];
    const int* src = edge_index;           // row 0 of [2,E]
    float* out = (float*)d_out;

    void* pU;
    cudaGetSymbolAddress(&pU, g_U);

    const int smemGemm = (DD * DD + 64 * DD) * (int)sizeof(float);   // 96 KB
    cudaFuncSetAttribute(k_combo1,     cudaFuncAttributeMaxDynamicSharedMemorySize, smemGemm);
    cudaFuncSetAttribute(k_combo2,     cudaFuncAttributeMaxDynamicSharedMemorySize, smemGemm);
    cudaFuncSetAttribute(k_gemm_final, cudaFuncAttributeMaxDynamicSharedMemorySize, smemGemm);

    const int zb = (NN + 127) / 128;
    k_prep<<<DD + 1 + zb, 128>>>(Wq, bq, Wk, bk, bv, Wo);                        // 1
    k_combo1<<<4 + (EE + 255) / 256, 256, smemGemm>>>(Wq, Wv, Wo, src);          // 2
    k_combo2<<<QPTILES + NBLK, 256, smemGemm>>>(node_feat);                      // 3
    k_pass1<<<EE / 32, 256>>>(time_feat, src, cemb);                             // 4 <- profiled
    k_scanC2<<<NBLK, 256>>>();                                                   // 5
    k_scatter<<<(EE + 255) / 256, 256>>>(src);                                   // 6
    k_pass2<<<(NN + P2_WPB - 1) / P2_WPB, 32 * P2_WPB>>>(time_feat);             // 7
    k_gemm_final<<<(NN + 63) / 64, 256, smemGemm>>>((const float*)pU, bo, out);  // 8
}

// round 13
// speedup vs baseline: 1.5938x; 1.0733x over previous
#include <cuda_runtime.h>
#include <math.h>

#define NN 50000
#define EE 600000
#define DD 128
#define CC 8
#define SCALEF 0.08838834764831845f   // 128^-0.5
#define NBLK 196                       // scan blocks: ceil(50000/256)
#define QPTILES 782                    // ceil(50000/64)

// ---------------- static device scratch ----------------
__device__ __align__(16) int   g_deg[NN];
__device__ __align__(16) int   g_rowptr[NN + 1];
__device__ __align__(16) int   g_cursor[NN];
__device__ __align__(16) int   g_eids[EE];
__device__ __align__(16) int   g_bsum[NBLK];
__device__ __align__(16) float g_WkT[DD * DD];
__device__ __align__(16) float g_Wqk[DD * DD];
__device__ __align__(16) float g_Wvo[DD * DD];
__device__ __align__(16) float g_bqk[DD];
__device__ __align__(16) float g_bvo[DD];
__device__ __align__(16) float g_wqbk[DD];
__device__            float g_bqbk;
__device__ __align__(16) float g_qp[(size_t)NN * DD];
__device__ __align__(16) float g_qb[NN];
__device__ __align__(16) float g_ex[EE];     // exp(attn), EDGE order
__device__ __align__(16) int   g_as[EE];     // cluster assign, EDGE order
__device__ __align__(16) int   g_cflag[CC];
__device__ __align__(16) float g_U[(size_t)NN * DD];
__device__ __align__(16) float g_S[NN];

// ---------------- packed f32x2 helpers ----------------
__device__ __forceinline__ unsigned long long pack2(float x) {
    unsigned long long r;
    unsigned u = __float_as_uint(x);
    asm("mov.b64 %0, {%1, %1};" : "=l"(r) : "r"(u));
    return r;
}
__device__ __forceinline__ void ffma2(unsigned long long& d, unsigned long long a,
                                      unsigned long long b) {
    asm("fma.rn.f32x2 %0, %1, %2, %0;" : "+l"(d) : "l"(a), "l"(b));
}
__device__ __forceinline__ void unpack2(unsigned long long v, float& lo, float& hi) {
    unsigned a, b;
    asm("mov.b64 {%0, %1}, %2;" : "=r"(a), "=r"(b) : "l"(v));
    lo = __uint_as_float(a); hi = __uint_as_float(b);
}
__device__ __forceinline__ float dot4(float4 a, float4 b) {
    return a.x * b.x + a.y * b.y + a.z * b.z + a.w * b.w;
}

// ---------------- prep + init fused ----------------
__global__ void k_prep(const float* __restrict__ Wq, const float* __restrict__ bq,
                       const float* __restrict__ Wk, const float* __restrict__ bk,
                       const float* __restrict__ bv, const float* __restrict__ Wo) {
    int b = blockIdx.x;
    if (b < DD) {
        int r = b, c = threadIdx.x;
        g_WkT[c * DD + r] = Wk[r * DD + c];
    } else if (b == DD) {
        int j = threadIdx.x;
        float s1 = 0.f, s2 = 0.f, s3 = 0.f;
        for (int l = 0; l < DD; l++) {
            s1 += bq[l] * Wk[j * DD + l];      // bqk  = bq @ Wk^T
            s2 += bv[l] * Wo[l * DD + j];      // bvo  = bv @ Wo
            s3 += Wq[j * DD + l] * bk[l];      // wqbk = Wq @ bk
        }
        g_bqk[j] = s1; g_bvo[j] = s2; g_wqbk[j] = s3;
        if (j < CC) g_cflag[j] = 0;
        if (j == 0) {
            float t = 0.f;
            for (int l = 0; l < DD; l++) t += bq[l] * bk[l];
            g_bqbk = t;
        }
    } else {
        int i = (b - DD - 1) * blockDim.x + threadIdx.x;
        if (i < NN) g_deg[i] = 0;
    }
}

// ---------------- shared GEMM tile helpers (64 rows x 128 cols, 256 thr) ----
__device__ __forceinline__ void dgemm_weight(const float* __restrict__ A,
                                             const float* __restrict__ W,
                                             float* __restrict__ out, int tile) {
    extern __shared__ float smem[];
    float4* Ws4 = (float4*)smem;
    float4* As4 = (float4*)(smem + DD * DD);
    const ulonglong2* WsU = (const ulonglong2*)smem;

    for (int i = threadIdx.x; i < DD * DD / 4; i += 256)
        Ws4[i] = ((const float4*)W)[i];
    int row0 = tile * 64;
    for (int i = threadIdx.x; i < 64 * 32; i += 256) {
        int rr = i >> 5, cc = i & 31;
        As4[i] = ((const float4*)A)[(size_t)(row0 + rr) * 32 + cc];
    }
    __syncthreads();

    int r = threadIdx.x >> 5;
    int jc = threadIdx.x & 31;

    unsigned long long acc2[8][2];
#pragma unroll
    for (int a = 0; a < 8; a++) { acc2[a][0] = 0ull; acc2[a][1] = 0ull; }

#pragma unroll 2
    for (int k4 = 0; k4 < 32; k4++) {
        float4 a4[8];
#pragma unroll
        for (int rr = 0; rr < 8; rr++) a4[rr] = As4[(r * 8 + rr) * 32 + k4];
#pragma unroll
        for (int kk = 0; kk < 4; kk++) {
            int k = k4 * 4 + kk;
            ulonglong2 w = WsU[k * 32 + jc];
#pragma unroll
            for (int rr = 0; rr < 8; rr++) {
                float av = (kk == 0) ? a4[rr].x : (kk == 1) ? a4[rr].y
                         : (kk == 2) ? a4[rr].z : a4[rr].w;
                unsigned long long av2 = pack2(av);
                ffma2(acc2[rr][0], av2, w.x);
                ffma2(acc2[rr][1], av2, w.y);
            }
        }
    }
#pragma unroll
    for (int rr = 0; rr < 8; rr++) {
        int row = row0 + r * 8 + rr;
        float o[4];
        unpack2(acc2[rr][0], o[0], o[1]);
        unpack2(acc2[rr][1], o[2], o[3]);
        ((float4*)out)[(size_t)row * 32 + jc] = make_float4(o[0], o[1], o[2], o[3]);
    }
}

__device__ __forceinline__ void dgemm_qp(const float* __restrict__ A, int tile) {
    extern __shared__ float smem[];
    float4* Ws4 = (float4*)smem;
    float4* As4 = (float4*)(smem + DD * DD);
    const ulonglong2* WsU = (const ulonglong2*)smem;

    for (int i = threadIdx.x; i < DD * DD / 4; i += 256)
        Ws4[i] = ((const float4*)g_Wqk)[i];
    int row0 = tile * 64;
    for (int i = threadIdx.x; i < 64 * 32; i += 256) {
        int rr = i >> 5, cc = i & 31;
        float4 v = make_float4(0.f, 0.f, 0.f, 0.f);
        if (row0 + rr < NN) v = ((const float4*)A)[(size_t)(row0 + rr) * 32 + cc];
        As4[i] = v;
    }
    __syncthreads();

    int r = threadIdx.x >> 5;
    int jc = threadIdx.x & 31;

    unsigned long long acc2[8][2];
#pragma unroll
    for (int a = 0; a < 8; a++) { acc2[a][0] = 0ull; acc2[a][1] = 0ull; }

#pragma unroll 2
    for (int k4 = 0; k4 < 32; k4++) {
        float4 a4[8];
#pragma unroll
        for (int rr = 0; rr < 8; rr++) a4[rr] = As4[(r * 8 + rr) * 32 + k4];
#pragma unroll
        for (int kk = 0; kk < 4; kk++) {
            int k = k4 * 4 + kk;
            ulonglong2 w = WsU[k * 32 + jc];
#pragma unroll
            for (int rr = 0; rr < 8; rr++) {
                float av = (kk == 0) ? a4[rr].x : (kk == 1) ? a4[rr].y
                         : (kk == 2) ? a4[rr].z : a4[rr].w;
                unsigned long long av2 = pack2(av);
                ffma2(acc2[rr][0], av2, w.x);
                ffma2(acc2[rr][1], av2, w.y);
            }
        }
    }

    // fused qb epilogue
    {
        float4 wq = ((const float4*)g_wqbk)[jc];
#pragma unroll
        for (int rr = 0; rr < 8; rr++) {
            int row = row0 + r * 8 + rr;
            float4 a0 = As4[(r * 8 + rr) * 32 + jc];
            float part = dot4(a0, wq);
#pragma unroll
            for (int off = 16; off; off >>= 1)
                part += __shfl_xor_sync(0xffffffffu, part, off);
            if (jc == 0 && row < NN) g_qb[row] = part + g_bqbk;
        }
    }

    float4 b0 = ((const float4*)g_bqk)[jc];
#pragma unroll
    for (int rr = 0; rr < 8; rr++) {
        int row = row0 + r * 8 + rr;
        if (row < NN) {
            float o[4];
            unpack2(acc2[rr][0], o[0], o[1]);
            unpack2(acc2[rr][1], o[2], o[3]);
            o[0] += b0.x; o[1] += b0.y; o[2] += b0.z; o[3] += b0.w;
            ((float4*)g_qp)[(size_t)row * 32 + jc] = make_float4(o[0], o[1], o[2], o[3]);
        }
    }
}

// ---------------- combo1: weight GEMMs + histogram ----------------
__global__ void __launch_bounds__(256, 2)
k_combo1(const float* __restrict__ Wq, const float* __restrict__ Wv,
         const float* __restrict__ Wo, const int* __restrict__ src) {
    if (blockIdx.x < 2) {
        dgemm_weight(Wq, g_WkT, g_Wqk, blockIdx.x);
    } else if (blockIdx.x < 4) {
        dgemm_weight(Wv, Wo, g_Wvo, blockIdx.x - 2);
    } else {
        int i = (blockIdx.x - 4) * 256 + threadIdx.x;
        if (i < EE) atomicAdd(&g_deg[src[i]], 1);
    }
}

// ---------------- combo2: qp GEMM + scanA ----------------
__global__ void __launch_bounds__(256, 2)
k_combo2(const float* __restrict__ nf) {
    if (blockIdx.x < QPTILES) {
        dgemm_qp(nf, blockIdx.x);
    } else {
        __shared__ int red[256];
        int sb = blockIdx.x - QPTILES;
        int i = sb * 256 + threadIdx.x;
        int v = (i < NN) ? g_deg[i] : 0;
        red[threadIdx.x] = v;
        __syncthreads();
        for (int off = 128; off; off >>= 1) {
            if (threadIdx.x < off) red[threadIdx.x] += red[threadIdx.x + off];
            __syncthreads();
        }
        if (threadIdx.x == 0) g_bsum[sb] = red[0];
    }
}

// ---------------- scanC2: per-block offset from bsum + local scan ----------
__global__ void k_scanC2() {
    __shared__ int s[256];
    __shared__ int s2[256];
    int tid = threadIdx.x, bid = blockIdx.x;
    int v = (tid < bid) ? g_bsum[tid] : 0;
    s2[tid] = v;
    __syncthreads();
    for (int off = 128; off; off >>= 1) {
        if (tid < off) s2[tid] += s2[tid + off];
        __syncthreads();
    }
    int base = s2[0];

    int i = bid * 256 + tid;
    int d = (i < NN) ? g_deg[i] : 0;
    s[tid] = d;
    __syncthreads();
    for (int off = 1; off < 256; off <<= 1) {
        int t = (tid >= off) ? s[tid - off] : 0;
        __syncthreads();
        s[tid] += t;
        __syncthreads();
    }
    if (i < NN) {
        int e = base + s[tid] - d;
        g_rowptr[i] = e;
        g_cursor[i] = e;
    }
    if (bid == NBLK - 1 && tid == 255) g_rowptr[NN] = base + s[255];
}

__global__ void k_scatter(const int* __restrict__ src) {
    int i = blockIdx.x * blockDim.x + threadIdx.x;
    if (i < EE) {
        int p = atomicAdd(&g_cursor[src[i]], 1);
        g_eids[p] = i;
    }
}

// ---------------- pass1: EDGE-ordered, 8 lanes/edge, 2 EDGES PER THREAD -----
// Warp handles 8 edges: thread (sub, l) owns edges e0 = gw*8+sub and e1 = e0+4.
// Each emb float4 is LDS-loaded ONCE and used for both edges -> emb LDS per
// edge halves (32 -> 16); total L1 ops per edge drop ~40%.
__global__ void __launch_bounds__(256, 3)
k_pass1(const float* __restrict__ tf, const int* __restrict__ src,
        const float* __restrict__ cemb) {
    __shared__ float4 emb_s[CC * 32];
    __shared__ int s_f[CC];
    if (threadIdx.x < CC) s_f[threadIdx.x] = 0;
    for (int i = threadIdx.x; i < CC * 32; i += blockDim.x)
        emb_s[i] = ((const float4*)cemb)[i];
    __syncthreads();

    int gw = (blockIdx.x * blockDim.x + threadIdx.x) >> 5;
    int lane = threadIdx.x & 31;
    int sub = lane >> 3;
    int l = lane & 7;
    int e0 = gw * 8 + sub;         // grid exact: EE % 8 == 0
    int e1 = e0 + 4;
    int s0 = __ldg(&src[e0]);
    int s1 = __ldg(&src[e1]);

    float4 t0[4], t1[4], q0[4], q1[4];
#pragma unroll
    for (int u = 0; u < 4; u++) {
        t0[u] = __ldg(&((const float4*)tf)[(size_t)e0 * 32 + u * 8 + l]);
        t1[u] = __ldg(&((const float4*)tf)[(size_t)e1 * 32 + u * 8 + l]);
        q0[u] = __ldg(&((const float4*)g_qp)[(size_t)s0 * 32 + u * 8 + l]);
        q1[u] = __ldg(&((const float4*)g_qp)[(size_t)s1 * 32 + u * 8 + l]);
    }

    float p0[CC + 1], p1[CC + 1];
#pragma unroll
    for (int c = 0; c < CC; c++) {
        float a0 = 0.f, a1 = 0.f;
#pragma unroll
        for (int u = 0; u < 4; u++) {
            float4 ev = emb_s[c * 32 + u * 8 + l];   // loaded once, used twice
            a0 += dot4(t0[u], ev);
            a1 += dot4(t1[u], ev);
        }
        p0[c] = a0; p1[c] = a1;
    }
    {
        float a0 = 0.f, a1 = 0.f;
#pragma unroll
        for (int u = 0; u < 4; u++) { a0 += dot4(t0[u], q0[u]); a1 += dot4(t1[u], q1[u]); }
        p0[CC] = a0; p1[CC] = a1;
    }

#pragma unroll
    for (int v = 0; v <= CC; v++) {
#pragma unroll
        for (int off = 4; off; off >>= 1) {
            p0[v] += __shfl_xor_sync(0xffffffffu, p0[v], off);
            p1[v] += __shfl_xor_sync(0xffffffffu, p1[v], off);
        }
    }

    if (l == 0) {
        int b0 = 0, b1 = 0; float m0 = p0[0], m1 = p1[0];
#pragma unroll
        for (int c = 1; c < CC; c++) {
            if (p0[c] > m0) { m0 = p0[c]; b0 = c; }
            if (p1[c] > m1) { m1 = p1[c]; b1 = c; }
        }
        g_ex[e0] = __expf((p0[CC] + __ldg(&g_qb[s0])) * SCALEF);
        g_ex[e1] = __expf((p1[CC] + __ldg(&g_qb[s1])) * SCALEF);
        g_as[e0] = b0;
        g_as[e1] = b1;
        s_f[b0] = 1;
        s_f[b1] = 1;
    }
    __syncthreads();
    if (threadIdx.x < CC && s_f[threadIdx.x]) g_cflag[threadIdx.x] = 1;
}

// ---------------- pass2: WARP per node (R9 shape; ex/as gathered via eid) ---
#define P2_WPB 8
__global__ void __launch_bounds__(32 * P2_WPB) k_pass2(const float* __restrict__ tf) {
    __shared__ float s_den[P2_WPB][CC];
    __shared__ int   s_cnt[P2_WPB][CC];

    int warp = threadIdx.x >> 5;
    int lane = threadIdx.x & 31;
    int n = blockIdx.x * P2_WPB + warp;
    if (n >= NN) return;

    if (lane < CC) { s_den[warp][lane] = 0.f; s_cnt[warp][lane] = 0; }
    __syncwarp();

    int beg = __ldg(&g_rowptr[n]);
    int deg = __ldg(&g_rowptr[n + 1]) - beg;
    int rounds = (deg + 31) >> 5;

    float4 acc = make_float4(0.f, 0.f, 0.f, 0.f);
    float sSum = 0.f;

    for (int r0 = 0; r0 < rounds; r0++) {
        int k = r0 * 32 + lane;
        bool on = k < deg;
        float ex = 0.f; int a = 0, eid = 0;
        if (on) {
            eid = __ldg(&g_eids[beg + k]);
            ex  = __ldg(&g_ex[eid]);
            a   = __ldg(&g_as[eid]);
            atomicAdd(&s_den[warp][a], ex);
            atomicAdd(&s_cnt[warp][a], 1);
        }
        __syncwarp();
        float cf = 0.f;
        if (on) cf = ex / (s_den[warp][a] * (float)s_cnt[warp][a]);
        if (rounds == 1) {
            sSum += cf;
            int cnt = deg;
#pragma unroll 4
            for (int kk = 0; kk < 32; kk++) {
                if (kk >= cnt) break;
                float c  = __shfl_sync(0xffffffffu, cf, kk);
                int   ee = __shfl_sync(0xffffffffu, eid, kk);
                float4 tv = __ldg(&((const float4*)tf)[(size_t)ee * 32 + lane]);
                acc.x += c * tv.x; acc.y += c * tv.y;
                acc.z += c * tv.z; acc.w += c * tv.w;
            }
        }
    }

    if (rounds > 1) {
        __syncwarp();
        for (int r0 = 0; r0 < rounds; r0++) {
            int k = r0 * 32 + lane;
            bool on = k < deg;
            float cf = 0.f; int eid = 0;
            if (on) {
                eid = __ldg(&g_eids[beg + k]);
                float ex = __ldg(&g_ex[eid]);
                int a = __ldg(&g_as[eid]);
                cf = ex / (s_den[warp][a] * (float)s_cnt[warp][a]);
            }
            sSum += cf;
            int cnt = deg - r0 * 32; if (cnt > 32) cnt = 32;
            for (int kk = 0; kk < cnt; kk++) {
                float c  = __shfl_sync(0xffffffffu, cf, kk);
                int   ee = __shfl_sync(0xffffffffu, eid, kk);
                float4 tv = __ldg(&((const float4*)tf)[(size_t)ee * 32 + lane]);
                acc.x += c * tv.x; acc.y += c * tv.y;
                acc.z += c * tv.z; acc.w += c * tv.w;
            }
        }
    }

    ((float4*)g_U)[(size_t)n * 32 + lane] = acc;

#pragma unroll
    for (int off = 16; off; off >>= 1) sSum += __shfl_xor_sync(0xffffffffu, sSum, off);
    if (lane == 0) g_S[n] = sSum;
}

// ---------------- final GEMM: out = relu(invnn*(U@Wvo + S*bvo) + bo) --------
__global__ void __launch_bounds__(256, 2)
k_gemm_final(const float* __restrict__ A, const float* __restrict__ bo,
             float* __restrict__ out) {
    extern __shared__ float smem[];
    float4* Ws4 = (float4*)smem;
    float4* As4 = (float4*)(smem + DD * DD);
    const ulonglong2* WsU = (const ulonglong2*)smem;

    for (int i = threadIdx.x; i < DD * DD / 4; i += 256)
        Ws4[i] = ((const float4*)g_Wvo)[i];
    __syncthreads();

    int r = threadIdx.x >> 5;
    int jc = threadIdx.x & 31;

    int nn = 0;
#pragma unroll
    for (int c = 0; c < CC; c++) nn += g_cflag[c];
    if (nn < 1) nn = 1;
    float gs = 1.f / (float)nn;

    int row0 = blockIdx.x * 64;
    for (int i = threadIdx.x; i < 64 * 32; i += 256) {
        int rr = i >> 5, cc = i & 31;
        float4 v = make_float4(0.f, 0.f, 0.f, 0.f);
        if (row0 + rr < NN) v = ((const float4*)A)[(size_t)(row0 + rr) * 32 + cc];
        As4[i] = v;
    }
    __syncthreads();

    unsigned long long acc2[8][2];
#pragma unroll
    for (int a = 0; a < 8; a++) { acc2[a][0] = 0ull; acc2[a][1] = 0ull; }

#pragma unroll 2
    for (int k4 = 0; k4 < 32; k4++) {
        float4 a4[8];
#pragma unroll
        for (int rr = 0; rr < 8; rr++) a4[rr] = As4[(r * 8 + rr) * 32 + k4];
#pragma unroll
        for (int kk = 0; kk < 4; kk++) {
            int k = k4 * 4 + kk;
            ulonglong2 w = WsU[k * 32 + jc];
#pragma unroll
            for (int rr = 0; rr < 8; rr++) {
                float av = (kk == 0) ? a4[rr].x : (kk == 1) ? a4[rr].y
                         : (kk == 2) ? a4[rr].z : a4[rr].w;
                unsigned long long av2 = pack2(av);
                ffma2(acc2[rr][0], av2, w.x);
                ffma2(acc2[rr][1], av2, w.y);
            }
        }
    }

    float4 b0 = ((const float4*)bo)[jc];
    float4 v0 = ((const float4*)g_bvo)[jc];

#pragma unroll
    for (int rr = 0; rr < 8; rr++) {
        int row = row0 + r * 8 + rr;
        if (row < NN) {
            float sc = g_S[row];
            float o[4];
            unpack2(acc2[rr][0], o[0], o[1]);
            unpack2(acc2[rr][1], o[2], o[3]);
            o[0] = fmaxf(gs * (o[0] + sc * v0.x) + b0.x, 0.f);
            o[1] = fmaxf(gs * (o[1] + sc * v0.y) + b0.y, 0.f);
            o[2] = fmaxf(gs * (o[2] + sc * v0.z) + b0.z, 0.f);
            o[3] = fmaxf(gs * (o[3] + sc * v0.w) + b0.w, 0.f);
            ((float4*)out)[(size_t)row * 32 + jc] = make_float4(o[0], o[1], o[2], o[3]);
        }
    }
}

// ---------------- launch ----------------
extern "C" void kernel_launch(void* const* d_in, const int* in_sizes, int n_in,
                              void* d_out, int out_size) {
    const float* node_feat = (const float*)d_in[0];
    const float* time_feat = (const float*)d_in[1];
    const int*   edge_index = (const int*)d_in[3];
    const float* Wq = (const float*)d_in[4];
    const float* bq = (const float*)d_in[5];
    const float* Wk = (const float*)d_in[6];
    const float* bk = (const float*)d_in[7];
    const float* Wv = (const float*)d_in[8];
    const float* bv = (const float*)d_in[9];
    const float* cemb = (const float*)d_in[10];
    const float* Wo = (const float*)d_in[11];
    const float* bo = (const float*)d_in[12];
    const int* src = edge_index;           // row 0 of [2,E]
    float* out = (float*)d_out;

    void* pU;
    cudaGetSymbolAddress(&pU, g_U);

    const int smemGemm = (DD * DD + 64 * DD) * (int)sizeof(float);   // 96 KB
    cudaFuncSetAttribute(k_combo1,     cudaFuncAttributeMaxDynamicSharedMemorySize, smemGemm);
    cudaFuncSetAttribute(k_combo2,     cudaFuncAttributeMaxDynamicSharedMemorySize, smemGemm);
    cudaFuncSetAttribute(k_gemm_final, cudaFuncAttributeMaxDynamicSharedMemorySize, smemGemm);

    const int zb = (NN + 127) / 128;
    k_prep<<<DD + 1 + zb, 128>>>(Wq, bq, Wk, bk, bv, Wo);                        // 1
    k_combo1<<<4 + (EE + 255) / 256, 256, smemGemm>>>(Wq, Wv, Wo, src);          // 2
    k_combo2<<<QPTILES + NBLK, 256, smemGemm>>>(node_feat);                      // 3
    k_pass1<<<EE / 64, 256>>>(time_feat, src, cemb);                             // 4 <- profiled
    k_scanC2<<<NBLK, 256>>>();                                                   // 5
    k_scatter<<<(EE + 255) / 256, 256>>>(src);                                   // 6
    k_pass2<<<(NN + P2_WPB - 1) / P2_WPB, 32 * P2_WPB>>>(time_feat);             // 7
    k_gemm_final<<<(NN + 63) / 64, 256, smemGemm>>>((const float*)pU, bo, out);  // 8
}